// round 4
// baseline (speedup 1.0000x reference)
#include <cuda_runtime.h>
#include <math.h>

#define LRW 256
#define LRH 256
#define HRW 1024
#define HRH 1024
#define NC 3
#define RAD 4

#define LRN (NC * LRH * LRW)
#define WP 1032            // padded HR width: 4 + 1024 + 4 (16B-aligned rows)
#define SROWS 1028         // vertical 5-sum rows: r = s+4, s in [-4, 1023]
#define SC (255.0f / 1023.0f)

// Scratch (no cudaMalloc allowed) — device globals.
__device__ float g_A[LRN];
__device__ float g_B[LRN];
__device__ float g_HL[NC * 2 * LRH * WP];     // horiz-upsampled A,b  (6.3 MB)
__device__ float g_S[NC * 2 * SROWS * WP];    // vertical 5-sums      (25.5 MB)
__device__ float g_U[NC * 2 * HRH * WP];      // full bilinear field  (25.4 MB)

// ---------------------------------------------------------------------------
// Helpers
// ---------------------------------------------------------------------------
__device__ __forceinline__ void load12(float* v, const float* base) {
    float4 q0 = *reinterpret_cast<const float4*>(base);
    float4 q1 = *reinterpret_cast<const float4*>(base + 4);
    float4 q2 = *reinterpret_cast<const float4*>(base + 8);
    v[0]=q0.x; v[1]=q0.y; v[2]=q0.z;  v[3]=q0.w;
    v[4]=q1.x; v[5]=q1.y; v[6]=q1.z;  v[7]=q1.w;
    v[8]=q2.x; v[9]=q2.y; v[10]=q2.z; v[11]=q2.w;
}

// h[i] = sum v[i..i+4], i = 0..7  (sliding 5-window)
__device__ __forceinline__ void hsum5(float* h, const float* v) {
    h[0] = v[0] + v[1] + v[2] + v[3] + v[4];
#pragma unroll
    for (int i = 1; i < 8; ++i) h[i] = h[i - 1] - v[i - 1] + v[i + 4];
}

__device__ __forceinline__ float4 f4axpy(float4 acc, float4 a, float s) {
    acc.x += a.x * s; acc.y += a.y * s; acc.z += a.z * s; acc.w += a.w * s;
    return acc;
}

// ---------------------------------------------------------------------------
// Fused low-res kernel (unchanged): tile 32x32 per block (grid 8x8x3).
// ---------------------------------------------------------------------------
#define LTS 32
#define LEX 40
#define LSP 44

__global__ void __launch_bounds__(256) lr_fused(const float* __restrict__ lrx,
                                                const float* __restrict__ lry,
                                                const float* __restrict__ boxw) {
    __shared__ __align__(16) float Xs[LEX * LSP];
    __shared__ __align__(16) float Ys[LEX * LSP];
    __shared__ __align__(16) float Vx[LTS * LSP];
    __shared__ __align__(16) float Vy[LTS * LSP];
    __shared__ __align__(16) float Vxy[LTS * LSP];
    __shared__ __align__(16) float Vxx[LTS * LSP];

    const int c = blockIdx.z;
    const int x0t = blockIdx.x * LTS;
    const int y0t = blockIdx.y * LTS;
    const int tid = threadIdx.x;
    const float* __restrict__ px = lrx + c * LRH * LRW;
    const float* __restrict__ py = lry + c * LRH * LRW;

    for (int j = tid; j < LEX * LEX; j += 256) {
        int ly = j / LEX, lx = j % LEX;
        int Y = y0t - RAD + ly; Y = Y < 0 ? 0 : (Y > LRH - 1 ? LRH - 1 : Y);
        int X = x0t - RAD + lx; X = X < 0 ? 0 : (X > LRW - 1 ? LRW - 1 : X);
        Xs[ly * LSP + lx] = px[Y * LRW + X];
        Ys[ly * LSP + lx] = py[Y * LRW + X];
    }
    __syncthreads();

    for (int j = tid; j < LTS * LEX; j += 256) {
        int ry = j / LEX, lx = j % LEX;
        float sx = 0.f, sy = 0.f, sxy = 0.f, sxx = 0.f;
#pragma unroll
        for (int k = 0; k < 9; ++k) {
            float vx = Xs[(ry + k) * LSP + lx];
            float vy = Ys[(ry + k) * LSP + lx];
            sx += vx; sy += vy; sxy += vx * vy; sxx += vx * vx;
        }
        Vx[ry * LSP + lx] = sx;  Vy[ry * LSP + lx] = sy;
        Vxy[ry * LSP + lx] = sxy; Vxx[ry * LSP + lx] = sxx;
    }
    __syncthreads();

    const int ty = tid >> 3;
    const int x0 = (tid & 7) << 2;
    float vx[12], vy[12], vxy[12], vxx[12];
    load12(vx,  &Vx[ty * LSP + x0]);
    load12(vy,  &Vy[ty * LSP + x0]);
    load12(vxy, &Vxy[ty * LSP + x0]);
    load12(vxx, &Vxx[ty * LSP + x0]);

    float hx[4], hy[4], hxy[4], hxx[4];
    hx[0] = vx[0]+vx[1]+vx[2]+vx[3]+vx[4]+vx[5]+vx[6]+vx[7]+vx[8];
    hy[0] = vy[0]+vy[1]+vy[2]+vy[3]+vy[4]+vy[5]+vy[6]+vy[7]+vy[8];
    hxy[0]= vxy[0]+vxy[1]+vxy[2]+vxy[3]+vxy[4]+vxy[5]+vxy[6]+vxy[7]+vxy[8];
    hxx[0]= vxx[0]+vxx[1]+vxx[2]+vxx[3]+vxx[4]+vxx[5]+vxx[6]+vxx[7]+vxx[8];
#pragma unroll
    for (int i = 1; i < 4; ++i) {
        hx[i]  = hx[i-1]  - vx[i-1]  + vx[i+8];
        hy[i]  = hy[i-1]  - vy[i-1]  + vy[i+8];
        hxy[i] = hxy[i-1] - vxy[i-1] + vxy[i+8];
        hxx[i] = hxx[i-1] - vxx[i-1] + vxx[i+8];
    }

    const float w = boxw[c * 81];
    float A_[4], B_[4];
#pragma unroll
    for (int p = 0; p < 4; ++p) {
        float mx = hx[p] * w, my = hy[p] * w, mxy = hxy[p] * w, mxx = hxx[p] * w;
        float A = (mxy - mx * my) / (mxx - mx * mx + 2.0f);   // EPS = 2
        A_[p] = A; B_[p] = my - A * mx;
    }
    int o = c * LRH * LRW + (y0t + ty) * LRW + (x0t + x0);
    *reinterpret_cast<float4*>(&g_A[o]) = make_float4(A_[0], A_[1], A_[2], A_[3]);
    *reinterpret_cast<float4*>(&g_B[o]) = make_float4(B_[0], B_[1], B_[2], B_[3]);
}

// ---------------------------------------------------------------------------
// HL: horizontal bilinear of A,b at padded HR columns, all 256 LR rows.
// One thread = 4 padded cols of one (channel, row). N = 3*256*258.
// ---------------------------------------------------------------------------
#define NGX (WP / 4)   // 258

__global__ void __launch_bounds__(256) hl_kernel() {
    int t = blockIdx.x * 256 + threadIdx.x;
    if (t >= NC * LRH * NGX) return;
    int xg = t % NGX;
    int j  = (t / NGX) % LRH;
    int c  = t / (NGX * LRH);

    const float* __restrict__ pA = g_A + (c * LRH + j) * LRW;
    const float* __restrict__ pB = g_B + (c * LRH + j) * LRW;

    float a[4], b[4];
#pragma unroll
    for (int p = 0; p < 4; ++p) {
        int X = xg * 4 + p - 4;              // padded -> unpadded
        X = X < 0 ? 0 : (X > HRW - 1 ? HRW - 1 : X);
        float tt = (float)X * SC;
        int ix = (int)floorf(tt); if (ix > LRW - 2) ix = LRW - 2;
        float fx = tt - (float)ix, ofx = 1.0f - fx;
        a[p] = pA[ix] * ofx + pA[ix + 1] * fx;
        b[p] = pB[ix] * ofx + pB[ix + 1] * fx;
    }
    int oA = ((c * 2 + 0) * LRH + j) * WP + xg * 4;
    int oB = ((c * 2 + 1) * LRH + j) * WP + xg * 4;
    *reinterpret_cast<float4*>(&g_HL[oA]) = make_float4(a[0], a[1], a[2], a[3]);
    *reinterpret_cast<float4*>(&g_HL[oB]) = make_float4(b[0], b[1], b[2], b[3]);
}

// ---------------------------------------------------------------------------
// SU: vertical 5-sums S(r) = sum_{k=0..4} Uext(r-4+k) as weighted HL rows,
// plus the center bilinear field U(y). One thread = 4 cols of one (c, r).
// N = 3 * 1028 * 258.
// ---------------------------------------------------------------------------
__global__ void __launch_bounds__(256) su_kernel() {
    int t = blockIdx.x * 256 + threadIdx.x;
    if (t >= NC * SROWS * NGX) return;
    int xg = t % NGX;
    int r  = (t / NGX) % SROWS;
    int c  = t / (NGX * SROWS);

    // vertical window weights onto <=4 consecutive LR rows
    int s = r - 4;
    float w0 = 0.f, w1 = 0.f, w2 = 0.f, w3 = 0.f;
    int j0 = 0;
#pragma unroll
    for (int k = 0; k < 5; ++k) {
        int Y = s + k; Y = Y < 0 ? 0 : (Y > HRH - 1 ? HRH - 1 : Y);
        float tt = (float)Y * SC;
        int iy = (int)floorf(tt); if (iy > LRH - 2) iy = LRH - 2;
        float fy = tt - (float)iy;
        if (k == 0) j0 = iy;
        int d = iy - j0;
        w0 += (d == 0) ? (1.0f - fy) : 0.0f;
        w1 += (d == 0) ? fy : ((d == 1) ? (1.0f - fy) : 0.0f);
        w2 += (d == 1) ? fy : ((d == 2) ? (1.0f - fy) : 0.0f);
        w3 += (d == 2) ? fy : 0.0f;
    }
    int j1 = j0 + 1;                       // j0 <= 254 so j1 <= 255
    int j2 = j0 + 2 > LRH - 1 ? LRH - 1 : j0 + 2;
    int j3 = j0 + 3 > LRH - 1 ? LRH - 1 : j0 + 3;

#pragma unroll
    for (int f = 0; f < 2; ++f) {
        const float* __restrict__ H = g_HL + (c * 2 + f) * LRH * WP + xg * 4;
        float4 acc = make_float4(0.f, 0.f, 0.f, 0.f);
        acc = f4axpy(acc, *reinterpret_cast<const float4*>(H + j0 * WP), w0);
        acc = f4axpy(acc, *reinterpret_cast<const float4*>(H + j1 * WP), w1);
        acc = f4axpy(acc, *reinterpret_cast<const float4*>(H + j2 * WP), w2);
        acc = f4axpy(acc, *reinterpret_cast<const float4*>(H + j3 * WP), w3);
        *reinterpret_cast<float4*>(
            &g_S[((c * 2 + f) * SROWS + r) * WP + xg * 4]) = acc;
    }

    if (r < HRH) {                         // center bilinear field U(y)
        float tt = (float)r * SC;
        int iy = (int)floorf(tt); if (iy > LRH - 2) iy = LRH - 2;
        float fy = tt - (float)iy, ofy = 1.0f - fy;
#pragma unroll
        for (int f = 0; f < 2; ++f) {
            const float* __restrict__ H = g_HL + (c * 2 + f) * LRH * WP + xg * 4;
            float4 u0 = *reinterpret_cast<const float4*>(H + iy * WP);
            float4 u1 = *reinterpret_cast<const float4*>(H + (iy + 1) * WP);
            float4 u = make_float4(u0.x * ofy + u1.x * fy, u0.y * ofy + u1.y * fy,
                                   u0.z * ofy + u1.z * fy, u0.w * ofy + u1.w * fy);
            *reinterpret_cast<float4*>(
                &g_U[((c * 2 + f) * HRH + r) * WP + xg * 4]) = u;
        }
    }
}

// ---------------------------------------------------------------------------
// Final: no smem, no barriers. One thread = 4 px of one row.
// top(y) = S[y], bot(y) = S[y+4], center = U[y]. All windows aligned LDG.128.
// grid (1024 rows, 3 channels), block 256.
// ---------------------------------------------------------------------------
__global__ void __launch_bounds__(256) final_kernel(const float* __restrict__ hrx,
                                                    float* __restrict__ out) {
    const int y = blockIdx.x;
    const int c = blockIdx.y;
    const int x0 = threadIdx.x * 4;        // padded base == unpadded x0-4 window

    const float* __restrict__ SA = g_S + (c * 2 + 0) * SROWS * WP + x0;
    const float* __restrict__ SB = g_S + (c * 2 + 1) * SROWS * WP + x0;
    const float* __restrict__ UA = g_U + ((c * 2 + 0) * HRH + y) * WP + x0;
    const float* __restrict__ UB = g_U + ((c * 2 + 1) * HRH + y) * WP + x0;

    float vAt[12], vAb[12], vAc[12], vBt[12], vBb[12], vBc[12];
    load12(vAt, SA + y * WP);
    load12(vAb, SA + (y + 4) * WP);
    load12(vAc, UA);
    load12(vBt, SB + y * WP);
    load12(vBb, SB + (y + 4) * WP);
    load12(vBc, UB);

    float hAt[8], hAb[8], hAc[8], hBt[8], hBb[8], hBc[8];
    hsum5(hAt, vAt); hsum5(hAb, vAb); hsum5(hAc, vAc);
    hsum5(hBt, vBt); hsum5(hBb, vBb); hsum5(hBc, vBc);

    const float4 im4 = *reinterpret_cast<const float4*>(
        &hrx[(c * HRH + y) * HRW + x0]);
    const float imv[4] = {im4.x, im4.y, im4.z, im4.w};

    const float i45 = 1.0f / 45.0f, i25 = 1.0f / 25.0f;
    float res[4];
#pragma unroll
    for (int p = 0; p < 4; ++p) {
        float atl = hAt[p], atr = hAt[p + 4];
        float abl = hAb[p], abr = hAb[p + 4];
        float acl = hAc[p], acr = hAc[p + 4];
        float btl = hBt[p], btr = hBt[p + 4];
        float bbl = hBb[p], bbr = hBb[p + 4];
        float bcl = hBc[p], bcr = hBc[p + 4];
        float atc = vAt[p + 4], abc = vAb[p + 4];
        float btc = vBt[p + 4], bbc = vBb[p + 4];

        float cA[8], cB[8];
        cA[0] = (atl + abl - acl) * i45;  cB[0] = (btl + bbl - bcl) * i45;  // L
        cA[1] = (atr + abr - acr) * i45;  cB[1] = (btr + bbr - bcr) * i45;  // R
        cA[2] = (atl + atr - atc) * i45;  cB[2] = (btl + btr - btc) * i45;  // U
        cA[3] = (abl + abr - abc) * i45;  cB[3] = (bbl + bbr - bbc) * i45;  // D
        cA[4] = atl * i25;                cB[4] = btl * i25;                // NW
        cA[5] = atr * i25;                cB[5] = btr * i25;                // NE
        cA[6] = abl * i25;                cB[6] = bbl * i25;                // SW
        cA[7] = abr * i25;                cB[7] = bbr * i25;                // SE

        const float im = imv[p];
        float best = cA[0] * im + cB[0] - im;
        float bestA = fabsf(best);
#pragma unroll
        for (int k = 1; k < 8; ++k) {
            float d = cA[k] * im + cB[k] - im;
            float ad = fabsf(d);
            if (ad < bestA) { bestA = ad; best = d; }  // strict '<' = first-min
        }
        float r = truncf(best + im);
        res[p] = fminf(fmaxf(r, 0.0f), 255.0f);
    }
    *reinterpret_cast<float4*>(&out[(c * HRH + y) * HRW + x0]) =
        make_float4(res[0], res[1], res[2], res[3]);
}

// ---------------------------------------------------------------------------
extern "C" void kernel_launch(void* const* d_in, const int* in_sizes, int n_in,
                              void* d_out, int out_size) {
    const float* lrx  = (const float*)d_in[0];
    const float* lry  = (const float*)d_in[1];
    const float* hrx  = (const float*)d_in[2];
    const float* boxw = (const float*)d_in[3];
    float* out = (float*)d_out;

    dim3 lgrid(LRW / LTS, LRH / LTS, NC);
    lr_fused<<<lgrid, 256>>>(lrx, lry, boxw);

    int n_hl = NC * LRH * NGX;
    hl_kernel<<<(n_hl + 255) / 256, 256>>>();

    int n_su = NC * SROWS * NGX;
    su_kernel<<<(n_su + 255) / 256, 256>>>();

    dim3 fgrid(HRH, NC);
    final_kernel<<<fgrid, 256>>>(hrx, out);
}

// round 5
// speedup vs baseline: 1.1655x; 1.1655x over previous
#include <cuda_runtime.h>
#include <math.h>

#define LRW 256
#define LRH 256
#define HRW 1024
#define HRH 1024
#define NC 3
#define RAD 4

#define LRN (NC * LRH * LRW)
#define WP 1032            // padded HR width: 4 + 1024 + 4
#define SC (255.0f / 1023.0f)

// Scratch (no cudaMalloc allowed) — device globals.
__device__ float g_A[LRN];
__device__ float g_B[LRN];
__device__ float g_HL[NC * 2 * LRH * WP];     // horiz-upsampled A,b (6.3 MB)

// ---------------------------------------------------------------------------
// Helpers
// ---------------------------------------------------------------------------
__device__ __forceinline__ void load12(float* v, const float* base) {
    float4 q0 = *reinterpret_cast<const float4*>(base);
    float4 q1 = *reinterpret_cast<const float4*>(base + 4);
    float4 q2 = *reinterpret_cast<const float4*>(base + 8);
    v[0]=q0.x; v[1]=q0.y; v[2]=q0.z;  v[3]=q0.w;
    v[4]=q1.x; v[5]=q1.y; v[6]=q1.z;  v[7]=q1.w;
    v[8]=q2.x; v[9]=q2.y; v[10]=q2.z; v[11]=q2.w;
}

// h[i] = sum v[i..i+4], i = 0..7  (sliding 5-window)
__device__ __forceinline__ void hsum5(float* h, const float* v) {
    h[0] = v[0] + v[1] + v[2] + v[3] + v[4];
#pragma unroll
    for (int i = 1; i < 8; ++i) h[i] = h[i - 1] - v[i - 1] + v[i + 4];
}

// ---------------------------------------------------------------------------
// Fused low-res kernel: tile 32x32 per block (grid 8x8x3), 256 threads.
// ---------------------------------------------------------------------------
#define LTS 32
#define LEX 40
#define LSP 44

__global__ void __launch_bounds__(256) lr_fused(const float* __restrict__ lrx,
                                                const float* __restrict__ lry,
                                                const float* __restrict__ boxw) {
    __shared__ __align__(16) float Xs[LEX * LSP];
    __shared__ __align__(16) float Ys[LEX * LSP];
    __shared__ __align__(16) float Vx[LTS * LSP];
    __shared__ __align__(16) float Vy[LTS * LSP];
    __shared__ __align__(16) float Vxy[LTS * LSP];
    __shared__ __align__(16) float Vxx[LTS * LSP];

    const int c = blockIdx.z;
    const int x0t = blockIdx.x * LTS;
    const int y0t = blockIdx.y * LTS;
    const int tid = threadIdx.x;
    const float* __restrict__ px = lrx + c * LRH * LRW;
    const float* __restrict__ py = lry + c * LRH * LRW;

    for (int j = tid; j < LEX * LEX; j += 256) {
        int ly = j / LEX, lx = j % LEX;
        int Y = y0t - RAD + ly; Y = Y < 0 ? 0 : (Y > LRH - 1 ? LRH - 1 : Y);
        int X = x0t - RAD + lx; X = X < 0 ? 0 : (X > LRW - 1 ? LRW - 1 : X);
        Xs[ly * LSP + lx] = px[Y * LRW + X];
        Ys[ly * LSP + lx] = py[Y * LRW + X];
    }
    __syncthreads();

    for (int j = tid; j < LTS * LEX; j += 256) {
        int ry = j / LEX, lx = j % LEX;
        float sx = 0.f, sy = 0.f, sxy = 0.f, sxx = 0.f;
#pragma unroll
        for (int k = 0; k < 9; ++k) {
            float vx = Xs[(ry + k) * LSP + lx];
            float vy = Ys[(ry + k) * LSP + lx];
            sx += vx; sy += vy; sxy += vx * vy; sxx += vx * vx;
        }
        Vx[ry * LSP + lx] = sx;  Vy[ry * LSP + lx] = sy;
        Vxy[ry * LSP + lx] = sxy; Vxx[ry * LSP + lx] = sxx;
    }
    __syncthreads();

    const int ty = tid >> 3;
    const int x0 = (tid & 7) << 2;
    float vx[12], vy[12], vxy[12], vxx[12];
    load12(vx,  &Vx[ty * LSP + x0]);
    load12(vy,  &Vy[ty * LSP + x0]);
    load12(vxy, &Vxy[ty * LSP + x0]);
    load12(vxx, &Vxx[ty * LSP + x0]);

    float hx[4], hy[4], hxy[4], hxx[4];
    hx[0] = vx[0]+vx[1]+vx[2]+vx[3]+vx[4]+vx[5]+vx[6]+vx[7]+vx[8];
    hy[0] = vy[0]+vy[1]+vy[2]+vy[3]+vy[4]+vy[5]+vy[6]+vy[7]+vy[8];
    hxy[0]= vxy[0]+vxy[1]+vxy[2]+vxy[3]+vxy[4]+vxy[5]+vxy[6]+vxy[7]+vxy[8];
    hxx[0]= vxx[0]+vxx[1]+vxx[2]+vxx[3]+vxx[4]+vxx[5]+vxx[6]+vxx[7]+vxx[8];
#pragma unroll
    for (int i = 1; i < 4; ++i) {
        hx[i]  = hx[i-1]  - vx[i-1]  + vx[i+8];
        hy[i]  = hy[i-1]  - vy[i-1]  + vy[i+8];
        hxy[i] = hxy[i-1] - vxy[i-1] + vxy[i+8];
        hxx[i] = hxx[i-1] - vxx[i-1] + vxx[i+8];
    }

    const float w = boxw[c * 81];
    float A_[4], B_[4];
#pragma unroll
    for (int p = 0; p < 4; ++p) {
        float mx = hx[p] * w, my = hy[p] * w, mxy = hxy[p] * w, mxx = hxx[p] * w;
        float A = (mxy - mx * my) / (mxx - mx * mx + 2.0f);   // EPS = 2
        A_[p] = A; B_[p] = my - A * mx;
    }
    int o = c * LRH * LRW + (y0t + ty) * LRW + (x0t + x0);
    *reinterpret_cast<float4*>(&g_A[o]) = make_float4(A_[0], A_[1], A_[2], A_[3]);
    *reinterpret_cast<float4*>(&g_B[o]) = make_float4(B_[0], B_[1], B_[2], B_[3]);
}

// ---------------------------------------------------------------------------
// HL: horizontal bilinear of A,b at padded HR columns, all 256 LR rows.
// ---------------------------------------------------------------------------
#define NGX (WP / 4)   // 258

__global__ void __launch_bounds__(256) hl_kernel() {
    int t = blockIdx.x * 256 + threadIdx.x;
    if (t >= NC * LRH * NGX) return;
    int xg = t % NGX;
    int j  = (t / NGX) % LRH;
    int c  = t / (NGX * LRH);

    const float* __restrict__ pA = g_A + (c * LRH + j) * LRW;
    const float* __restrict__ pB = g_B + (c * LRH + j) * LRW;

    float a[4], b[4];
#pragma unroll
    for (int p = 0; p < 4; ++p) {
        int X = xg * 4 + p - 4;              // padded -> unpadded
        X = X < 0 ? 0 : (X > HRW - 1 ? HRW - 1 : X);
        float tt = (float)X * SC;
        int ix = (int)floorf(tt); if (ix > LRW - 2) ix = LRW - 2;
        float fx = tt - (float)ix, ofx = 1.0f - fx;
        a[p] = pA[ix] * ofx + pA[ix + 1] * fx;
        b[p] = pB[ix] * ofx + pB[ix + 1] * fx;
    }
    int oA = ((c * 2 + 0) * LRH + j) * WP + xg * 4;
    int oB = ((c * 2 + 1) * LRH + j) * WP + xg * 4;
    *reinterpret_cast<float4*>(&g_HL[oA]) = make_float4(a[0], a[1], a[2], a[3]);
    *reinterpret_cast<float4*>(&g_HL[oB]) = make_float4(b[0], b[1], b[2], b[3]);
}

// ---------------------------------------------------------------------------
// HR fused: block = 128-col x 16-row tile (grid 8x64x3), 256 threads.
// Phase W: per-block vertical weight tables (S rows, center rows).
// Phase F: S rows (vertical 5-sums = <=4-row weighted HL combos) and U rows
//          (HL row lerp) -> shared memory. S/U never touch global.
// Phase 3: 2 groups of 4 px per thread; warp = one output row.
// ---------------------------------------------------------------------------
#define XT 128
#define YS 16
#define SMP 140          // smem row stride (floats); 136 used
#define NQ 34            // 136 / 4 float4 groups
#define SR 20            // S rows: r in [Y0, Y0+19]
#define UR 16
#define UOFF (2 * SR * SMP)
#define NS_ITEMS (2 * SR * NQ)   // 1360
#define NU_ITEMS (2 * UR * NQ)   // 1088

__global__ void __launch_bounds__(256, 3) hr_fused(const float* __restrict__ hrx,
                                                   float* __restrict__ out) {
    __shared__ __align__(16) float sm[(2 * SR + 2 * UR) * SMP];  // 40.3 KB
    __shared__ int    s_j0[SR];
    __shared__ float4 s_w[SR];
    __shared__ int    s_ciy[UR];
    __shared__ float  s_cfy[UR];

    const int c  = blockIdx.z;
    const int X0 = blockIdx.x * XT;      // output col base == padded col base
    const int Y0 = blockIdx.y * YS;
    const int tid = threadIdx.x;

    // ---- Phase W: weight tables ----
    if (tid < SR) {                       // S row r = Y0 + tid: HR rows r-4..r
        int r = Y0 + tid;
        float w0 = 0.f, w1 = 0.f, w2 = 0.f, w3 = 0.f;
        int j0 = 0;
#pragma unroll
        for (int k = 0; k < 5; ++k) {
            int Y = r - 4 + k; Y = Y < 0 ? 0 : (Y > HRH - 1 ? HRH - 1 : Y);
            float tt = (float)Y * SC;
            int iy = (int)floorf(tt); if (iy > LRH - 2) iy = LRH - 2;
            float fy = tt - (float)iy;
            if (k == 0) j0 = iy;
            int d = iy - j0;
            w0 += (d == 0) ? (1.0f - fy) : 0.0f;
            w1 += (d == 0) ? fy : ((d == 1) ? (1.0f - fy) : 0.0f);
            w2 += (d == 1) ? fy : ((d == 2) ? (1.0f - fy) : 0.0f);
            w3 += (d == 2) ? fy : 0.0f;
        }
        s_j0[tid] = j0;
        s_w[tid] = make_float4(w0, w1, w2, w3);
    } else if (tid >= 32 && tid < 32 + UR) {   // center rows
        int y = Y0 + (tid - 32);
        float tt = (float)y * SC;
        int iy = (int)floorf(tt); if (iy > LRH - 2) iy = LRH - 2;
        s_ciy[tid - 32] = iy;
        s_cfy[tid - 32] = tt - (float)iy;
    }
    __syncthreads();

    // ---- Phase F: fill S and U rows in smem ----
    const float* __restrict__ HLc = g_HL + (size_t)(c * 2) * LRH * WP + X0;
    for (int it = tid; it < NS_ITEMS + NU_ITEMS; it += 256) {
        if (it < NS_ITEMS) {
            int f  = it / (SR * NQ);
            int rm = it - f * (SR * NQ);
            int rr = rm / NQ;
            int q  = rm - rr * NQ;
            int j0 = s_j0[rr];
            float4 w = s_w[rr];
            const float* H = HLc + (size_t)f * LRH * WP + q * 4;
            int j1 = j0 + 1;
            int j2 = j0 + 2 > LRH - 1 ? LRH - 1 : j0 + 2;
            int j3 = j0 + 3 > LRH - 1 ? LRH - 1 : j0 + 3;
            float4 h0 = *reinterpret_cast<const float4*>(H + j0 * WP);
            float4 h1 = *reinterpret_cast<const float4*>(H + j1 * WP);
            float4 h2 = *reinterpret_cast<const float4*>(H + j2 * WP);
            float4 h3 = *reinterpret_cast<const float4*>(H + j3 * WP);
            float4 acc;
            acc.x = h0.x*w.x + h1.x*w.y + h2.x*w.z + h3.x*w.w;
            acc.y = h0.y*w.x + h1.y*w.y + h2.y*w.z + h3.y*w.w;
            acc.z = h0.z*w.x + h1.z*w.y + h2.z*w.z + h3.z*w.w;
            acc.w = h0.w*w.x + h1.w*w.y + h2.w*w.z + h3.w*w.w;
            *reinterpret_cast<float4*>(&sm[(f * SR + rr) * SMP + q * 4]) = acc;
        } else {
            int it2 = it - NS_ITEMS;
            int f  = it2 / (UR * NQ);
            int rm = it2 - f * (UR * NQ);
            int rr = rm / NQ;
            int q  = rm - rr * NQ;
            int iy = s_ciy[rr];
            float fy = s_cfy[rr], ofy = 1.0f - fy;
            const float* H = HLc + (size_t)f * LRH * WP + q * 4;
            float4 u0 = *reinterpret_cast<const float4*>(H + iy * WP);
            float4 u1 = *reinterpret_cast<const float4*>(H + (iy + 1) * WP);
            float4 u;
            u.x = u0.x*ofy + u1.x*fy; u.y = u0.y*ofy + u1.y*fy;
            u.z = u0.z*ofy + u1.z*fy; u.w = u0.w*ofy + u1.w*fy;
            *reinterpret_cast<float4*>(&sm[UOFF + (f * UR + rr) * SMP + q * 4]) = u;
        }
    }
    __syncthreads();

    // ---- Phase 3: 2 groups of 4 px per thread; warp == one row ----
    const float i45 = 1.0f / 45.0f, i25 = 1.0f / 25.0f;
#pragma unroll
    for (int g = 0; g < 2; ++g) {
        int G = g * 256 + tid;
        int row = G >> 5;                // 0..15
        int xl  = (G & 31) << 2;         // 0..124

        float vAt[12], vAb[12], vAc[12], vBt[12], vBb[12], vBc[12];
        load12(vAt, &sm[(0 * SR + row) * SMP + xl]);
        load12(vAb, &sm[(0 * SR + row + 4) * SMP + xl]);
        load12(vBt, &sm[(1 * SR + row) * SMP + xl]);
        load12(vBb, &sm[(1 * SR + row + 4) * SMP + xl]);
        load12(vAc, &sm[UOFF + (0 * UR + row) * SMP + xl]);
        load12(vBc, &sm[UOFF + (1 * UR + row) * SMP + xl]);

        float hAt[8], hAb[8], hAc[8], hBt[8], hBb[8], hBc[8];
        hsum5(hAt, vAt); hsum5(hAb, vAb); hsum5(hAc, vAc);
        hsum5(hBt, vBt); hsum5(hBb, vBb); hsum5(hBc, vBc);

        const int Y = Y0 + row, X = X0 + xl;
        const float4 im4 = *reinterpret_cast<const float4*>(
            &hrx[(c * HRH + Y) * HRW + X]);
        const float imv[4] = {im4.x, im4.y, im4.z, im4.w};

        float res[4];
#pragma unroll
        for (int p = 0; p < 4; ++p) {
            float atl = hAt[p], atr = hAt[p + 4];
            float abl = hAb[p], abr = hAb[p + 4];
            float acl = hAc[p], acr = hAc[p + 4];
            float btl = hBt[p], btr = hBt[p + 4];
            float bbl = hBb[p], bbr = hBb[p + 4];
            float bcl = hBc[p], bcr = hBc[p + 4];
            float atc = vAt[p + 4], abc = vAb[p + 4];
            float btc = vBt[p + 4], bbc = vBb[p + 4];

            float cA[8], cB[8];
            cA[0] = (atl + abl - acl) * i45;  cB[0] = (btl + bbl - bcl) * i45;  // L
            cA[1] = (atr + abr - acr) * i45;  cB[1] = (btr + bbr - bcr) * i45;  // R
            cA[2] = (atl + atr - atc) * i45;  cB[2] = (btl + btr - btc) * i45;  // U
            cA[3] = (abl + abr - abc) * i45;  cB[3] = (bbl + bbr - bbc) * i45;  // D
            cA[4] = atl * i25;                cB[4] = btl * i25;                // NW
            cA[5] = atr * i25;                cB[5] = btr * i25;                // NE
            cA[6] = abl * i25;                cB[6] = bbl * i25;                // SW
            cA[7] = abr * i25;                cB[7] = bbr * i25;                // SE

            const float im = imv[p];
            float best = cA[0] * im + cB[0] - im;
            float bestA = fabsf(best);
#pragma unroll
            for (int k = 1; k < 8; ++k) {
                float d = cA[k] * im + cB[k] - im;
                float ad = fabsf(d);
                if (ad < bestA) { bestA = ad; best = d; }  // strict '<' = first-min
            }
            float r = truncf(best + im);
            res[p] = fminf(fmaxf(r, 0.0f), 255.0f);
        }
        *reinterpret_cast<float4*>(&out[(c * HRH + Y) * HRW + X]) =
            make_float4(res[0], res[1], res[2], res[3]);
    }
}

// ---------------------------------------------------------------------------
extern "C" void kernel_launch(void* const* d_in, const int* in_sizes, int n_in,
                              void* d_out, int out_size) {
    const float* lrx  = (const float*)d_in[0];
    const float* lry  = (const float*)d_in[1];
    const float* hrx  = (const float*)d_in[2];
    const float* boxw = (const float*)d_in[3];
    float* out = (float*)d_out;

    dim3 lgrid(LRW / LTS, LRH / LTS, NC);
    lr_fused<<<lgrid, 256>>>(lrx, lry, boxw);

    int n_hl = NC * LRH * NGX;
    hl_kernel<<<(n_hl + 255) / 256, 256>>>();

    dim3 grid(HRW / XT, HRH / YS, NC);
    hr_fused<<<grid, 256>>>(hrx, out);
}

// round 6
// speedup vs baseline: 1.2321x; 1.0571x over previous
#include <cuda_runtime.h>
#include <math.h>

#define LRW 256
#define LRH 256
#define HRW 1024
#define HRH 1024
#define NC 3
#define RAD 4

#define LRN (NC * LRH * LRW)
#define WP 1032            // padded HR width: 4 + 1024 + 4
#define SC (255.0f / 1023.0f)

// Scratch (no cudaMalloc allowed) — device globals.
__device__ float g_A[LRN];
__device__ float g_B[LRN];
__device__ float g_HL[NC * 2 * LRH * WP];     // horiz-upsampled A,b (6.3 MB)

// ---------------------------------------------------------------------------
// Helpers
// ---------------------------------------------------------------------------
__device__ __forceinline__ void load12(float* v, const float* base) {
    float4 q0 = *reinterpret_cast<const float4*>(base);
    float4 q1 = *reinterpret_cast<const float4*>(base + 4);
    float4 q2 = *reinterpret_cast<const float4*>(base + 8);
    v[0]=q0.x; v[1]=q0.y; v[2]=q0.z;  v[3]=q0.w;
    v[4]=q1.x; v[5]=q1.y; v[6]=q1.z;  v[7]=q1.w;
    v[8]=q2.x; v[9]=q2.y; v[10]=q2.z; v[11]=q2.w;
}

// h[i] = sum v[i..i+4], i = 0..7  (sliding 5-window)
__device__ __forceinline__ void hsum5(float* h, const float* v) {
    h[0] = v[0] + v[1] + v[2] + v[3] + v[4];
#pragma unroll
    for (int i = 1; i < 8; ++i) h[i] = h[i - 1] - v[i - 1] + v[i + 4];
}

// ---------------------------------------------------------------------------
// Fused low-res kernel: tile 16x16 per block (grid 16x16x3 = 768 blocks),
// 128 threads. Small tiles -> ~5 blocks/SM so barrier phases overlap.
// ---------------------------------------------------------------------------
#define LTS 16
#define LEX 24
#define LSP 28

__global__ void __launch_bounds__(128) lr_fused(const float* __restrict__ lrx,
                                                const float* __restrict__ lry,
                                                const float* __restrict__ boxw) {
    __shared__ __align__(16) float Xs[LEX * LSP];
    __shared__ __align__(16) float Ys[LEX * LSP];
    __shared__ __align__(16) float Vx[LTS * LSP];
    __shared__ __align__(16) float Vy[LTS * LSP];
    __shared__ __align__(16) float Vxy[LTS * LSP];
    __shared__ __align__(16) float Vxx[LTS * LSP];

    const int c = blockIdx.z;
    const int x0t = blockIdx.x * LTS;
    const int y0t = blockIdx.y * LTS;
    const int tid = threadIdx.x;
    const float* __restrict__ px = lrx + c * LRH * LRW;
    const float* __restrict__ py = lry + c * LRH * LRW;

    for (int j = tid; j < LEX * LEX; j += 128) {
        int ly = j / LEX, lx = j % LEX;
        int Y = y0t - RAD + ly; Y = Y < 0 ? 0 : (Y > LRH - 1 ? LRH - 1 : Y);
        int X = x0t - RAD + lx; X = X < 0 ? 0 : (X > LRW - 1 ? LRW - 1 : X);
        Xs[ly * LSP + lx] = px[Y * LRW + X];
        Ys[ly * LSP + lx] = py[Y * LRW + X];
    }
    __syncthreads();

    for (int j = tid; j < LTS * LEX; j += 128) {
        int ry = j / LEX, lx = j % LEX;
        float sx = 0.f, sy = 0.f, sxy = 0.f, sxx = 0.f;
#pragma unroll
        for (int k = 0; k < 9; ++k) {
            float vx = Xs[(ry + k) * LSP + lx];
            float vy = Ys[(ry + k) * LSP + lx];
            sx += vx; sy += vy; sxy += vx * vy; sxx += vx * vx;
        }
        Vx[ry * LSP + lx] = sx;  Vy[ry * LSP + lx] = sy;
        Vxy[ry * LSP + lx] = sxy; Vxx[ry * LSP + lx] = sxx;
    }
    __syncthreads();

    if (tid < 64) {
        const int ty = tid >> 2;            // 0..15
        const int x0 = (tid & 3) << 2;      // 0,4,8,12
        float vx[12], vy[12], vxy[12], vxx[12];
        load12(vx,  &Vx[ty * LSP + x0]);
        load12(vy,  &Vy[ty * LSP + x0]);
        load12(vxy, &Vxy[ty * LSP + x0]);
        load12(vxx, &Vxx[ty * LSP + x0]);

        float hx[4], hy[4], hxy[4], hxx[4];
        hx[0] = vx[0]+vx[1]+vx[2]+vx[3]+vx[4]+vx[5]+vx[6]+vx[7]+vx[8];
        hy[0] = vy[0]+vy[1]+vy[2]+vy[3]+vy[4]+vy[5]+vy[6]+vy[7]+vy[8];
        hxy[0]= vxy[0]+vxy[1]+vxy[2]+vxy[3]+vxy[4]+vxy[5]+vxy[6]+vxy[7]+vxy[8];
        hxx[0]= vxx[0]+vxx[1]+vxx[2]+vxx[3]+vxx[4]+vxx[5]+vxx[6]+vxx[7]+vxx[8];
#pragma unroll
        for (int i = 1; i < 4; ++i) {
            hx[i]  = hx[i-1]  - vx[i-1]  + vx[i+8];
            hy[i]  = hy[i-1]  - vy[i-1]  + vy[i+8];
            hxy[i] = hxy[i-1] - vxy[i-1] + vxy[i+8];
            hxx[i] = hxx[i-1] - vxx[i-1] + vxx[i+8];
        }

        const float w = boxw[c * 81];
        float A_[4], B_[4];
#pragma unroll
        for (int p = 0; p < 4; ++p) {
            float mx = hx[p] * w, my = hy[p] * w, mxy = hxy[p] * w, mxx = hxx[p] * w;
            float A = (mxy - mx * my) / (mxx - mx * mx + 2.0f);   // EPS = 2
            A_[p] = A; B_[p] = my - A * mx;
        }
        int o = c * LRH * LRW + (y0t + ty) * LRW + (x0t + x0);
        *reinterpret_cast<float4*>(&g_A[o]) = make_float4(A_[0], A_[1], A_[2], A_[3]);
        *reinterpret_cast<float4*>(&g_B[o]) = make_float4(B_[0], B_[1], B_[2], B_[3]);
    }
}

// ---------------------------------------------------------------------------
// HL: horizontal bilinear of A,b at padded HR columns, all 256 LR rows.
// ---------------------------------------------------------------------------
#define NGX (WP / 4)   // 258

__global__ void __launch_bounds__(256) hl_kernel() {
    int t = blockIdx.x * 256 + threadIdx.x;
    if (t >= NC * LRH * NGX) return;
    int xg = t % NGX;
    int j  = (t / NGX) % LRH;
    int c  = t / (NGX * LRH);

    const float* __restrict__ pA = g_A + (c * LRH + j) * LRW;
    const float* __restrict__ pB = g_B + (c * LRH + j) * LRW;

    float a[4], b[4];
#pragma unroll
    for (int p = 0; p < 4; ++p) {
        int X = xg * 4 + p - 4;              // padded -> unpadded
        X = X < 0 ? 0 : (X > HRW - 1 ? HRW - 1 : X);
        float tt = (float)X * SC;
        int ix = (int)floorf(tt); if (ix > LRW - 2) ix = LRW - 2;
        float fx = tt - (float)ix, ofx = 1.0f - fx;
        a[p] = pA[ix] * ofx + pA[ix + 1] * fx;
        b[p] = pB[ix] * ofx + pB[ix + 1] * fx;
    }
    int oA = ((c * 2 + 0) * LRH + j) * WP + xg * 4;
    int oB = ((c * 2 + 1) * LRH + j) * WP + xg * 4;
    *reinterpret_cast<float4*>(&g_HL[oA]) = make_float4(a[0], a[1], a[2], a[3]);
    *reinterpret_cast<float4*>(&g_HL[oB]) = make_float4(b[0], b[1], b[2], b[3]);
}

// ---------------------------------------------------------------------------
// HR fused: block = 128-col x 16-row tile (grid 8x64x3), 256 threads.
// Phase W: per-block vertical weight tables (S rows, center rows).
// Phase F: S rows (vertical 5-sums = <=4-row weighted HL combos) and U rows
//          (HL row lerp) -> shared memory.
// Phase 3: 2 groups of 4 px per thread; P-trick direction assembly.
// ---------------------------------------------------------------------------
#define XT 128
#define YS 16
#define SMP 140          // smem row stride (floats); 136 used
#define NQ 34            // 136 / 4 float4 groups
#define SR 20            // S rows: r in [Y0, Y0+19]
#define UR 16
#define UOFF (2 * SR * SMP)
#define NS_ITEMS (2 * SR * NQ)   // 1360
#define NU_ITEMS (2 * UR * NQ)   // 1088

__global__ void __launch_bounds__(256, 3) hr_fused(const float* __restrict__ hrx,
                                                   float* __restrict__ out) {
    __shared__ __align__(16) float sm[(2 * SR + 2 * UR) * SMP];  // 40.3 KB
    __shared__ int    s_j0[SR];
    __shared__ float4 s_w[SR];
    __shared__ int    s_ciy[UR];
    __shared__ float  s_cfy[UR];

    const int c  = blockIdx.z;
    const int X0 = blockIdx.x * XT;
    const int Y0 = blockIdx.y * YS;
    const int tid = threadIdx.x;

    // ---- Phase W: weight tables ----
    if (tid < SR) {                       // S row r = Y0 + tid: HR rows r-4..r
        int r = Y0 + tid;
        float w0 = 0.f, w1 = 0.f, w2 = 0.f, w3 = 0.f;
        int j0 = 0;
#pragma unroll
        for (int k = 0; k < 5; ++k) {
            int Y = r - 4 + k; Y = Y < 0 ? 0 : (Y > HRH - 1 ? HRH - 1 : Y);
            float tt = (float)Y * SC;
            int iy = (int)floorf(tt); if (iy > LRH - 2) iy = LRH - 2;
            float fy = tt - (float)iy;
            if (k == 0) j0 = iy;
            int d = iy - j0;
            w0 += (d == 0) ? (1.0f - fy) : 0.0f;
            w1 += (d == 0) ? fy : ((d == 1) ? (1.0f - fy) : 0.0f);
            w2 += (d == 1) ? fy : ((d == 2) ? (1.0f - fy) : 0.0f);
            w3 += (d == 2) ? fy : 0.0f;
        }
        s_j0[tid] = j0;
        s_w[tid] = make_float4(w0, w1, w2, w3);
    } else if (tid >= 32 && tid < 32 + UR) {   // center rows
        int y = Y0 + (tid - 32);
        float tt = (float)y * SC;
        int iy = (int)floorf(tt); if (iy > LRH - 2) iy = LRH - 2;
        s_ciy[tid - 32] = iy;
        s_cfy[tid - 32] = tt - (float)iy;
    }
    __syncthreads();

    // ---- Phase F: fill S and U rows in smem ----
    const float* __restrict__ HLc = g_HL + (size_t)(c * 2) * LRH * WP + X0;
    for (int it = tid; it < NS_ITEMS + NU_ITEMS; it += 256) {
        if (it < NS_ITEMS) {
            int f  = it / (SR * NQ);
            int rm = it - f * (SR * NQ);
            int rr = rm / NQ;
            int q  = rm - rr * NQ;
            int j0 = s_j0[rr];
            float4 w = s_w[rr];
            const float* H = HLc + (size_t)f * LRH * WP + q * 4;
            int j1 = j0 + 1;
            int j2 = j0 + 2 > LRH - 1 ? LRH - 1 : j0 + 2;
            int j3 = j0 + 3 > LRH - 1 ? LRH - 1 : j0 + 3;
            float4 h0 = *reinterpret_cast<const float4*>(H + j0 * WP);
            float4 h1 = *reinterpret_cast<const float4*>(H + j1 * WP);
            float4 h2 = *reinterpret_cast<const float4*>(H + j2 * WP);
            float4 h3 = *reinterpret_cast<const float4*>(H + j3 * WP);
            float4 acc;
            acc.x = h0.x*w.x + h1.x*w.y + h2.x*w.z + h3.x*w.w;
            acc.y = h0.y*w.x + h1.y*w.y + h2.y*w.z + h3.y*w.w;
            acc.z = h0.z*w.x + h1.z*w.y + h2.z*w.z + h3.z*w.w;
            acc.w = h0.w*w.x + h1.w*w.y + h2.w*w.z + h3.w*w.w;
            *reinterpret_cast<float4*>(&sm[(f * SR + rr) * SMP + q * 4]) = acc;
        } else {
            int it2 = it - NS_ITEMS;
            int f  = it2 / (UR * NQ);
            int rm = it2 - f * (UR * NQ);
            int rr = rm / NQ;
            int q  = rm - rr * NQ;
            int iy = s_ciy[rr];
            float fy = s_cfy[rr], ofy = 1.0f - fy;
            const float* H = HLc + (size_t)f * LRH * WP + q * 4;
            float4 u0 = *reinterpret_cast<const float4*>(H + iy * WP);
            float4 u1 = *reinterpret_cast<const float4*>(H + (iy + 1) * WP);
            float4 u;
            u.x = u0.x*ofy + u1.x*fy; u.y = u0.y*ofy + u1.y*fy;
            u.z = u0.z*ofy + u1.z*fy; u.w = u0.w*ofy + u1.w*fy;
            *reinterpret_cast<float4*>(&sm[UOFF + (f * UR + rr) * SMP + q * 4]) = u;
        }
    }
    __syncthreads();

    // ---- Phase 3: 2 groups of 4 px per thread; warp == one row ----
    const float i45 = 1.0f / 45.0f, i25 = 1.0f / 25.0f;
#pragma unroll
    for (int g = 0; g < 2; ++g) {
        int G = g * 256 + tid;
        int row = G >> 5;                // 0..15
        int xl  = (G & 31) << 2;         // 0..124

        float vAt[12], vAb[12], vAc[12], vBt[12], vBb[12], vBc[12];
        load12(vAt, &sm[(0 * SR + row) * SMP + xl]);
        load12(vAb, &sm[(0 * SR + row + 4) * SMP + xl]);
        load12(vBt, &sm[(1 * SR + row) * SMP + xl]);
        load12(vBb, &sm[(1 * SR + row + 4) * SMP + xl]);
        load12(vAc, &sm[UOFF + (0 * UR + row) * SMP + xl]);
        load12(vBc, &sm[UOFF + (1 * UR + row) * SMP + xl]);

        float hAt[8], hAb[8], hAc[8], hBt[8], hBb[8], hBc[8];
        hsum5(hAt, vAt); hsum5(hAb, vAb); hsum5(hAc, vAc);
        hsum5(hBt, vBt); hsum5(hBb, vBb); hsum5(hBc, vBc);

        const int Y = Y0 + row, X = X0 + xl;
        const float4 im4 = *reinterpret_cast<const float4*>(
            &hrx[(c * HRH + Y) * HRW + X]);
        const float imv[4] = {im4.x, im4.y, im4.z, im4.w};

        float res[4];
#pragma unroll
        for (int p = 0; p < 4; ++p) {
            const float im = imv[p];
            // P-trick: fold im once per partial sum, then each direction is
            // one combo + one fma with -im.
            float Ptl = fmaf(hAt[p],     im, hBt[p]);
            float Ptr = fmaf(hAt[p + 4], im, hBt[p + 4]);
            float Pbl = fmaf(hAb[p],     im, hBb[p]);
            float Pbr = fmaf(hAb[p + 4], im, hBb[p + 4]);
            float Pcl = fmaf(hAc[p],     im, hBc[p]);
            float Pcr = fmaf(hAc[p + 4], im, hBc[p + 4]);
            float Ptc = fmaf(vAt[p + 4], im, vBt[p + 4]);
            float Pbc = fmaf(vAb[p + 4], im, vBb[p + 4]);

            float d0 = fmaf(Ptl + Pbl - Pcl, i45, -im);  // L
            float d1 = fmaf(Ptr + Pbr - Pcr, i45, -im);  // R
            float d2 = fmaf(Ptl + Ptr - Ptc, i45, -im);  // U
            float d3 = fmaf(Pbl + Pbr - Pbc, i45, -im);  // D
            float d4 = fmaf(Ptl, i25, -im);              // NW
            float d5 = fmaf(Ptr, i25, -im);              // NE
            float d6 = fmaf(Pbl, i25, -im);              // SW
            float d7 = fmaf(Pbr, i25, -im);              // SE

            float best = d0, bestA = fabsf(d0), ad;
            ad = fabsf(d1); if (ad < bestA) { bestA = ad; best = d1; }
            ad = fabsf(d2); if (ad < bestA) { bestA = ad; best = d2; }
            ad = fabsf(d3); if (ad < bestA) { bestA = ad; best = d3; }
            ad = fabsf(d4); if (ad < bestA) { bestA = ad; best = d4; }
            ad = fabsf(d5); if (ad < bestA) { bestA = ad; best = d5; }
            ad = fabsf(d6); if (ad < bestA) { bestA = ad; best = d6; }
            ad = fabsf(d7); if (ad < bestA) { bestA = ad; best = d7; }

            float r = truncf(best + im);
            res[p] = fminf(fmaxf(r, 0.0f), 255.0f);
        }
        *reinterpret_cast<float4*>(&out[(c * HRH + Y) * HRW + X]) =
            make_float4(res[0], res[1], res[2], res[3]);
    }
}

// ---------------------------------------------------------------------------
extern "C" void kernel_launch(void* const* d_in, const int* in_sizes, int n_in,
                              void* d_out, int out_size) {
    const float* lrx  = (const float*)d_in[0];
    const float* lry  = (const float*)d_in[1];
    const float* hrx  = (const float*)d_in[2];
    const float* boxw = (const float*)d_in[3];
    float* out = (float*)d_out;

    dim3 lgrid(LRW / LTS, LRH / LTS, NC);
    lr_fused<<<lgrid, 128>>>(lrx, lry, boxw);

    int n_hl = NC * LRH * NGX;
    hl_kernel<<<(n_hl + 255) / 256, 256>>>();

    dim3 grid(HRW / XT, HRH / YS, NC);
    hr_fused<<<grid, 256>>>(hrx, out);
}